// round 4
// baseline (speedup 1.0000x reference)
#include <cuda_runtime.h>

// DimeNetBlock fused kernel, round 4 (= round 3 resubmit; R3 was infra fail).
// Root cause of R1/R2 crash: edge_index is int32 (JAX x64 disabled), was read
// with int64 stride -> OOB. Dtype detected on device (1-thread kernel).
// Decomposition:
//   edge:  h_e = silu([rbf_e, angle_e] @ W1 + b1)           (E x 64)
//          scatter: S[row] += h_e ; deg[row] += 1
//   node:  agg = S @ W2 + deg*b2                            (W2 moved out of E-space)
//          out = x + silu(agg @ W3 + b3) @ W4 + b4

#define NNODE 100000
constexpr int EMB = 64;

__device__ __align__(16) float g_agg[(size_t)NNODE * 64];
__device__ __align__(16) float g_deg[NNODE];
__device__ int g_is64;

__device__ __forceinline__ float fsig(float x) {
    float e;
    asm("ex2.approx.f32 %0, %1;" : "=f"(e) : "f"(-1.4426950408889634f * x));
    float r;
    asm("rcp.approx.f32 %0, %1;" : "=f"(r) : "f"(1.0f + e));
    return r;
}

// ---------------------------------------------------------------------------
// Detect index dtype: view first 8 elements as int64. If really int32, high
// words contain neighboring indices (nonzero whp) -> int64 view >= N.
// ---------------------------------------------------------------------------
__global__ void detect_kernel(const long long* __restrict__ e64, int N) {
    bool ok = true;
#pragma unroll
    for (int i = 0; i < 8; i++) {       // 64 bytes, in bounds for either dtype
        long long v = e64[i];
        if (v < 0 || v >= (long long)N) ok = false;
    }
    g_is64 = ok ? 1 : 0;
}

// ---------------------------------------------------------------------------
// Zero the scatter buffers (graph replays reuse them).
// ---------------------------------------------------------------------------
__global__ void zero_kernel() {
    int i = blockIdx.x * blockDim.x + threadIdx.x;
    const int AGG4 = NNODE * 64 / 4;
    const int DEG4 = NNODE / 4;
    if (i < AGG4) {
        reinterpret_cast<float4*>(g_agg)[i] = make_float4(0.f, 0.f, 0.f, 0.f);
    } else if (i < AGG4 + DEG4) {
        reinterpret_cast<float4*>(g_deg)[i - AGG4] = make_float4(0.f, 0.f, 0.f, 0.f);
    }
}

// ---------------------------------------------------------------------------
// Edge kernel: 4 threads per edge, 16 output columns per thread.
// ---------------------------------------------------------------------------
__global__ void __launch_bounds__(256) edge_kernel(
    const float* __restrict__ rbf, const float* __restrict__ coord,
    const void* __restrict__ eidx_raw,
    const float* __restrict__ W1, const float* __restrict__ b1, int E)
{
    __shared__ __align__(16) float W1s[17 * 64];
    __shared__ __align__(16) float b1s[64];
    __shared__ int is64s;
    for (int i = threadIdx.x; i < 17 * 64; i += blockDim.x) W1s[i] = W1[i];
    if (threadIdx.x < 64) b1s[threadIdx.x] = b1[threadIdx.x];
    if (threadIdx.x == 0) is64s = g_is64;
    __syncthreads();

    int t   = blockIdx.x * blockDim.x + threadIdx.x;
    int e   = t >> 2;
    int sub = t & 3;
    int lane = threadIdx.x & 31;
    bool valid = (e < E);
    if (!valid) e = 0;   // whole 4-thread group clamps together

    int row, col;
    if (is64s) {
        const long long* e64 = (const long long*)eidx_raw;
        row = (int)e64[e];
        col = (int)e64[(size_t)E + e];
    } else {
        const int* e32 = (const int*)eidx_raw;
        row = e32[e];
        col = e32[(size_t)E + e];
    }

    // angle(v, -v) exactly as reference: normalize, -dot, clip, acos
    float vx = coord[row * 3 + 0] - coord[col * 3 + 0];
    float vy = coord[row * 3 + 1] - coord[col * 3 + 1];
    float vz = coord[row * 3 + 2] - coord[col * 3 + 2];
    float nrm = fmaxf(sqrtf(vx * vx + vy * vy + vz * vz), 1e-12f);
    float ux = vx / nrm, uy = vy / nrm, uz = vz / nrm;
    float s  = ux * ux + uy * uy + uz * uz;
    float ca = fminf(fmaxf(-s, -1.0f + 1e-8f), 1.0f - 1e-8f);
    float angle = acosf(ca);

    float4 myr = reinterpret_cast<const float4*>(rbf)[(size_t)e * 4 + sub];

    float acc[16];
#pragma unroll
    for (int i = 0; i < 16; i++) acc[i] = b1s[sub * 16 + i];

#pragma unroll
    for (int k = 0; k < 17; k++) {
        float fk;
        if (k < 16) {
            float comp = ((k & 3) == 0) ? myr.x : ((k & 3) == 1) ? myr.y
                       : ((k & 3) == 2) ? myr.z : myr.w;
            fk = __shfl_sync(0xffffffffu, comp, (lane & ~3) | (k >> 2), 32);
        } else {
            fk = angle;
        }
        const float4* wr = reinterpret_cast<const float4*>(&W1s[k * 64 + sub * 16]);
#pragma unroll
        for (int i = 0; i < 4; i++) {
            float4 w = wr[i];
            acc[4 * i + 0] += fk * w.x;
            acc[4 * i + 1] += fk * w.y;
            acc[4 * i + 2] += fk * w.z;
            acc[4 * i + 3] += fk * w.w;
        }
    }

#pragma unroll
    for (int i = 0; i < 16; i++) {
        float v = acc[i];
        acc[i] = v * fsig(v);
    }

    if (valid) {
        float* dst = &g_agg[(size_t)row * 64 + sub * 16];
#pragma unroll
        for (int i = 0; i < 4; i++) {
            asm volatile("red.global.add.v4.f32 [%0], {%1,%2,%3,%4};" ::
                         "l"(dst + 4 * i),
                         "f"(acc[4 * i + 0]), "f"(acc[4 * i + 1]),
                         "f"(acc[4 * i + 2]), "f"(acc[4 * i + 3]) : "memory");
        }
        if (sub == 0) {
            asm volatile("red.global.add.f32 [%0], %1;" ::
                         "l"(&g_deg[row]), "f"(1.0f) : "memory");
        }
    }
}

// ---------------------------------------------------------------------------
// Node kernel: one warp per node, 2 columns per lane, three 64x64 matvecs.
// ---------------------------------------------------------------------------
__device__ __forceinline__ float2 mv64(const float* __restrict__ Ws, float2 v,
                                       float2 init, int lane)
{
    float a0 = init.x, a1 = init.y;
#pragma unroll
    for (int k = 0; k < 64; k++) {
        float xk = __shfl_sync(0xffffffffu, (k & 1) ? v.y : v.x, k >> 1, 32);
        float2 w = reinterpret_cast<const float2*>(Ws + k * 64)[lane];
        a0 += xk * w.x;
        a1 += xk * w.y;
    }
    return make_float2(a0, a1);
}

__global__ void __launch_bounds__(256) node_kernel(
    const float* __restrict__ x,
    const float* __restrict__ W2, const float* __restrict__ b2,
    const float* __restrict__ W3, const float* __restrict__ b3,
    const float* __restrict__ W4, const float* __restrict__ b4,
    float* __restrict__ out, int N)
{
    __shared__ __align__(16) float Ws[3 * 64 * 64];   // 48KB
    for (int i = threadIdx.x; i < 4096; i += 256) {
        Ws[i]        = W2[i];
        Ws[4096 + i] = W3[i];
        Ws[8192 + i] = W4[i];
    }
    __syncthreads();

    int lane = threadIdx.x & 31;
    int warp = threadIdx.x >> 5;
    float2 bb2 = reinterpret_cast<const float2*>(b2)[lane];
    float2 bb3 = reinterpret_cast<const float2*>(b3)[lane];
    float2 bb4 = reinterpret_cast<const float2*>(b4)[lane];

    for (int n = blockIdx.x * 8 + warp; n < N; n += gridDim.x * 8) {
        float2 S  = reinterpret_cast<const float2*>(g_agg)[(size_t)n * 32 + lane];
        float  dg = g_deg[n];

        float2 a = mv64(Ws,        S, make_float2(dg * bb2.x, dg * bb2.y), lane);
        float2 p = mv64(Ws + 4096, a, bb3, lane);
        p.x *= fsig(p.x);
        p.y *= fsig(p.y);
        float2 q = mv64(Ws + 8192, p, bb4, lane);

        float2 xv = reinterpret_cast<const float2*>(x)[(size_t)n * 32 + lane];
        reinterpret_cast<float2*>(out)[(size_t)n * 32 + lane] =
            make_float2(xv.x + q.x, xv.y + q.y);
    }
}

// ---------------------------------------------------------------------------
extern "C" void kernel_launch(void* const* d_in, const int* in_sizes, int n_in,
                              void* d_out, int out_size)
{
    const float* x     = (const float*)d_in[0];
    const float* coord = (const float*)d_in[1];
    const float* rbf   = (const float*)d_in[2];
    const void*  eidx  = d_in[3];
    const float* W1 = (const float*)d_in[4];
    const float* b1 = (const float*)d_in[5];
    const float* W2 = (const float*)d_in[6];
    const float* b2 = (const float*)d_in[7];
    const float* W3 = (const float*)d_in[8];
    const float* b3 = (const float*)d_in[9];
    const float* W4 = (const float*)d_in[10];
    const float* b4 = (const float*)d_in[11];
    float* out = (float*)d_out;

    int E = in_sizes[3] / 2;
    int N = in_sizes[0] / EMB;

    detect_kernel<<<1, 1>>>((const long long*)eidx, N);
    {
        int total4 = NNODE * 64 / 4 + NNODE / 4;
        zero_kernel<<<(total4 + 255) / 256, 256>>>();
    }
    {
        long long threads = (long long)E * 4;
        int blocks = (int)((threads + 255) / 256);
        edge_kernel<<<blocks, 256>>>(rbf, coord, eidx, W1, b1, E);
    }
    node_kernel<<<592, 256>>>(x, W2, b2, W3, b3, W4, b4, out, N);
}

// round 5
// speedup vs baseline: 1.7817x; 1.7817x over previous
#include <cuda_runtime.h>

// DimeNetBlock, round 5: counting-sort CSR + warp-per-node gather (no fp32
// atomics), W1 in registers, 8-node-blocked node kernel.
// Pipeline:
//   detect -> zero counts -> histogram(row) -> scan(3 kernels) -> permute
//   -> edge_gather (per-node: sum_e silu([rbf_e,angle_e]@W1+b1) -> g_S, deg from CSR)
//   -> node: out = x + silu((g_S@W2 + deg*b2)@W3+b3)@W4 + b4

#define NNODE 100000
#define NEDGE 3200000
constexpr int EMB = 64;

__device__ __align__(16) float g_S[(size_t)NNODE * 64];
__device__ int g_cnt[NNODE + 1];
__device__ int g_off[NNODE + 1];
__device__ int g_woff[NNODE];
__device__ int g_sorted[NEDGE];
__device__ int g_blk[256];
__device__ int g_blkoff[256];
__device__ int g_is64;

__device__ __forceinline__ float fsig(float x) {
    float e;
    asm("ex2.approx.f32 %0, %1;" : "=f"(e) : "f"(-1.4426950408889634f * x));
    float r;
    asm("rcp.approx.f32 %0, %1;" : "=f"(r) : "f"(1.0f + e));
    return r;
}

__device__ __forceinline__ int load_row(const void* eidx_raw, int e, int is64) {
    if (is64) return (int)((const long long*)eidx_raw)[e];
    return ((const int*)eidx_raw)[e];
}

// ---------------------------------------------------------------------------
__global__ void detect_kernel(const long long* __restrict__ e64, int N) {
    bool ok = true;
#pragma unroll
    for (int i = 0; i < 8; i++) {
        long long v = e64[i];
        if (v < 0 || v >= (long long)N) ok = false;
    }
    g_is64 = ok ? 1 : 0;
}

__global__ void zero_cnt_kernel(int N) {
    int i = blockIdx.x * blockDim.x + threadIdx.x;
    if (i <= N) g_cnt[i] = 0;
}

__global__ void hist_kernel(const void* __restrict__ eidx_raw, int E) {
    int e = blockIdx.x * blockDim.x + threadIdx.x;
    if (e >= E) return;
    int r = load_row(eidx_raw, e, g_is64);
    atomicAdd(&g_cnt[r], 1);
}

// ---- scan: 512-wide chunks --------------------------------------------------
__global__ void scan_a_kernel(int N) {        // per-chunk sums -> g_blk
    __shared__ int s[512];
    int i = blockIdx.x * 512 + threadIdx.x;
    s[threadIdx.x] = (i < N) ? g_cnt[i] : 0;
    __syncthreads();
    for (int d = 256; d > 0; d >>= 1) {
        if (threadIdx.x < d) s[threadIdx.x] += s[threadIdx.x + d];
        __syncthreads();
    }
    if (threadIdx.x == 0) g_blk[blockIdx.x] = s[0];
}

__global__ void scan_b_kernel(int nblk, int N) {   // scan chunk sums
    __shared__ int sa[256], sb[256];
    int t = threadIdx.x;
    int v = (t < nblk) ? g_blk[t] : 0;
    sa[t] = v;
    __syncthreads();
    int* src = sa; int* dst = sb;
    for (int d = 1; d < 256; d <<= 1) {
        dst[t] = src[t] + ((t >= d) ? src[t - d] : 0);
        __syncthreads();
        int* tmp = src; src = dst; dst = tmp;
    }
    if (t < nblk) g_blkoff[t] = src[t] - v;          // exclusive
    if (t == nblk - 1) g_off[N] = src[t];            // total == E
}

__global__ void scan_c_kernel(int N) {        // final exclusive offsets
    __shared__ int sa[512], sb[512];
    int t = threadIdx.x;
    int i = blockIdx.x * 512 + t;
    int v = (i < N) ? g_cnt[i] : 0;
    sa[t] = v;
    __syncthreads();
    int* src = sa; int* dst = sb;
    for (int d = 1; d < 512; d <<= 1) {
        dst[t] = src[t] + ((t >= d) ? src[t - d] : 0);
        __syncthreads();
        int* tmp = src; src = dst; dst = tmp;
    }
    if (i < N) {
        int off = g_blkoff[blockIdx.x] + src[t] - v;
        g_off[i]  = off;
        g_woff[i] = off;
    }
}

__global__ void permute_kernel(const void* __restrict__ eidx_raw, int E) {
    int e = blockIdx.x * blockDim.x + threadIdx.x;
    if (e >= E) return;
    int r = load_row(eidx_raw, e, g_is64);
    int p = atomicAdd(&g_woff[r], 1);
    g_sorted[p] = e;
}

// ---------------------------------------------------------------------------
// Edge gather: one warp per node. Lane owns 2 output cols (W1 in 34 regs).
// Per 32-edge chunk: each lane computes its own edge's angle; rbf features
// loaded 8-edges-per-batch, double-buffered, broadcast via shfl.
// ---------------------------------------------------------------------------
__global__ void __launch_bounds__(256) edge_gather_kernel(
    const float* __restrict__ rbf, const float* __restrict__ coord,
    const void* __restrict__ eidx_raw,
    const float* __restrict__ W1, const float* __restrict__ b1, int E, int N)
{
    __shared__ int is64s;
    if (threadIdx.x == 0) is64s = g_is64;
    __syncthreads();

    const int lane = threadIdx.x & 31;
    const int wid  = threadIdx.x >> 5;
    const int i64  = is64s;

    float2 w1r[17];
#pragma unroll
    for (int k = 0; k < 17; k++)
        w1r[k] = *(const float2*)&W1[k * 64 + 2 * lane];
    float2 b1r = *(const float2*)&b1[2 * lane];

    const int*       c32 = (const int*)eidx_raw + E;
    const long long* c64 = (const long long*)eidx_raw + E;

    for (int n = blockIdx.x * 8 + wid; n < N; n += gridDim.x * 8) {
        int s0 = g_off[n], s1 = g_off[n + 1];
        float rx = coord[3 * n], ry = coord[3 * n + 1], rz = coord[3 * n + 2];
        float accx = 0.f, accy = 0.f;

        for (int base = s0; base < s1; base += 32) {
            int m = min(32, s1 - base);
            int eidv = g_sorted[min(base + lane, s1 - 1)];

            // per-lane own-edge angle (exact reference chain)
            int c = i64 ? (int)c64[eidv] : c32[eidv];
            float vx = rx - coord[3 * c];
            float vy = ry - coord[3 * c + 1];
            float vz = rz - coord[3 * c + 2];
            float nrm = fmaxf(sqrtf(vx * vx + vy * vy + vz * vz), 1e-12f);
            float ux = vx / nrm, uy = vy / nrm, uz = vz / nrm;
            float sq = ux * ux + uy * uy + uz * uz;
            float ca = fminf(fmaxf(-sq, -1.0f + 1e-8f), 1.0f - 1e-8f);
            float angle = acosf(ca);

            // batch-0 feature prefetch: reg r holds edge r*2 + (lane>>4),
            // feature k = lane&15
            float f_cur[4], f_nxt[4];
#pragma unroll
            for (int r = 0; r < 4; r++) {
                int i = r * 2 + (lane >> 4);
                int es = __shfl_sync(0xffffffffu, eidv, min(i, 31));
                f_cur[r] = rbf[(size_t)es * 16 + (lane & 15)];
            }

            int nb = (m + 7) >> 3;
            for (int b = 0; b < nb; b++) {
                if (b + 1 < nb) {
#pragma unroll
                    for (int r = 0; r < 4; r++) {
                        int i = (b + 1) * 8 + r * 2 + (lane >> 4);
                        int es = __shfl_sync(0xffffffffu, eidv, min(i, 31));
                        f_nxt[r] = rbf[(size_t)es * 16 + (lane & 15)];
                    }
                }
#pragma unroll
                for (int j = 0; j < 8; j++) {
                    int i = b * 8 + j;
                    float hx = b1r.x, hy = b1r.y;
#pragma unroll
                    for (int k = 0; k < 16; k++) {
                        float fk = __shfl_sync(0xffffffffu, f_cur[j >> 1],
                                               ((j & 1) << 4) | k);
                        hx = fmaf(fk, w1r[k].x, hx);
                        hy = fmaf(fk, w1r[k].y, hy);
                    }
                    float ang = __shfl_sync(0xffffffffu, angle, i);
                    hx = fmaf(ang, w1r[16].x, hx);
                    hy = fmaf(ang, w1r[16].y, hy);
                    if (i < m) {               // uniform branch (i, m scalar)
                        accx += hx * fsig(hx);
                        accy += hy * fsig(hy);
                    }
                }
#pragma unroll
                for (int r = 0; r < 4; r++) f_cur[r] = f_nxt[r];
            }
        }
        *(float2*)&g_S[(size_t)n * 64 + 2 * lane] = make_float2(accx, accy);
    }
}

// ---------------------------------------------------------------------------
// Node kernel: warp processes 8 nodes at once (weight LDS amortized 8x).
// Lane owns cols (2*lane, 2*lane+1). deg = off[n+1]-off[n].
// ---------------------------------------------------------------------------
__global__ void __launch_bounds__(256) node_kernel(
    const float* __restrict__ x,
    const float* __restrict__ W2, const float* __restrict__ b2,
    const float* __restrict__ W3, const float* __restrict__ b3,
    const float* __restrict__ W4, const float* __restrict__ b4,
    float* __restrict__ out, int N)
{
    __shared__ __align__(16) float Ws[3 * 64 * 64];   // 48KB
    for (int i = threadIdx.x; i < 4096; i += 256) {
        Ws[i]        = W2[i];
        Ws[4096 + i] = W3[i];
        Ws[8192 + i] = W4[i];
    }
    __syncthreads();

    int lane = threadIdx.x & 31;
    int wid  = threadIdx.x >> 5;
    float2 bb2 = *(const float2*)&b2[2 * lane];
    float2 bb3 = *(const float2*)&b3[2 * lane];
    float2 bb4 = *(const float2*)&b4[2 * lane];

    for (int g = blockIdx.x * 8 + wid; g * 8 < N; g += gridDim.x * 8) {
        int n0 = g * 8;
        float2 v[8];
        float  dg[8];
#pragma unroll
        for (int t = 0; t < 8; t++) {
            int n = n0 + t;
            if (n < N) {
                v[t]  = *(const float2*)&g_S[(size_t)n * 64 + 2 * lane];
                dg[t] = (float)(g_off[n + 1] - g_off[n]);
            } else {
                v[t] = make_float2(0.f, 0.f); dg[t] = 0.f;
            }
        }

        float2 a[8];
#pragma unroll
        for (int t = 0; t < 8; t++)
            a[t] = make_float2(dg[t] * bb2.x, dg[t] * bb2.y);

        // stage A: a = S @ W2 + deg*b2
#pragma unroll 4
        for (int kk = 0; kk < 32; kk++) {
            float2 w0 = *(const float2*)&Ws[(2 * kk)     * 64 + 2 * lane];
            float2 w1 = *(const float2*)&Ws[(2 * kk + 1) * 64 + 2 * lane];
#pragma unroll
            for (int t = 0; t < 8; t++) {
                float x0 = __shfl_sync(0xffffffffu, v[t].x, kk);
                float x1 = __shfl_sync(0xffffffffu, v[t].y, kk);
                a[t].x = fmaf(x0, w0.x, fmaf(x1, w1.x, a[t].x));
                a[t].y = fmaf(x0, w0.y, fmaf(x1, w1.y, a[t].y));
            }
        }

        // stage B: p = silu(a @ W3 + b3)
        float2 p[8];
#pragma unroll
        for (int t = 0; t < 8; t++) p[t] = bb3;
#pragma unroll 4
        for (int kk = 0; kk < 32; kk++) {
            float2 w0 = *(const float2*)&Ws[4096 + (2 * kk)     * 64 + 2 * lane];
            float2 w1 = *(const float2*)&Ws[4096 + (2 * kk + 1) * 64 + 2 * lane];
#pragma unroll
            for (int t = 0; t < 8; t++) {
                float x0 = __shfl_sync(0xffffffffu, a[t].x, kk);
                float x1 = __shfl_sync(0xffffffffu, a[t].y, kk);
                p[t].x = fmaf(x0, w0.x, fmaf(x1, w1.x, p[t].x));
                p[t].y = fmaf(x0, w0.y, fmaf(x1, w1.y, p[t].y));
            }
        }
#pragma unroll
        for (int t = 0; t < 8; t++) {
            p[t].x *= fsig(p[t].x);
            p[t].y *= fsig(p[t].y);
        }

        // stage C: q = p @ W4 + b4 ; out = x + q
        float2 q[8];
#pragma unroll
        for (int t = 0; t < 8; t++) q[t] = bb4;
#pragma unroll 4
        for (int kk = 0; kk < 32; kk++) {
            float2 w0 = *(const float2*)&Ws[8192 + (2 * kk)     * 64 + 2 * lane];
            float2 w1 = *(const float2*)&Ws[8192 + (2 * kk + 1) * 64 + 2 * lane];
#pragma unroll
            for (int t = 0; t < 8; t++) {
                float x0 = __shfl_sync(0xffffffffu, p[t].x, kk);
                float x1 = __shfl_sync(0xffffffffu, p[t].y, kk);
                q[t].x = fmaf(x0, w0.x, fmaf(x1, w1.x, q[t].x));
                q[t].y = fmaf(x0, w0.y, fmaf(x1, w1.y, q[t].y));
            }
        }
#pragma unroll
        for (int t = 0; t < 8; t++) {
            int n = n0 + t;
            if (n < N) {
                float2 xv = *(const float2*)&x[(size_t)n * 64 + 2 * lane];
                *(float2*)&out[(size_t)n * 64 + 2 * lane] =
                    make_float2(xv.x + q[t].x, xv.y + q[t].y);
            }
        }
    }
}

// ---------------------------------------------------------------------------
extern "C" void kernel_launch(void* const* d_in, const int* in_sizes, int n_in,
                              void* d_out, int out_size)
{
    const float* x     = (const float*)d_in[0];
    const float* coord = (const float*)d_in[1];
    const float* rbf   = (const float*)d_in[2];
    const void*  eidx  = d_in[3];
    const float* W1 = (const float*)d_in[4];
    const float* b1 = (const float*)d_in[5];
    const float* W2 = (const float*)d_in[6];
    const float* b2 = (const float*)d_in[7];
    const float* W3 = (const float*)d_in[8];
    const float* b3 = (const float*)d_in[9];
    const float* W4 = (const float*)d_in[10];
    const float* b4 = (const float*)d_in[11];
    float* out = (float*)d_out;

    int E = in_sizes[3] / 2;
    int N = in_sizes[0] / EMB;
    int nblk = (N + 511) / 512;

    detect_kernel<<<1, 1>>>((const long long*)eidx, N);
    zero_cnt_kernel<<<(N + 256) / 256, 256>>>(N);
    hist_kernel<<<(E + 255) / 256, 256>>>(eidx, E);
    scan_a_kernel<<<nblk, 512>>>(N);
    scan_b_kernel<<<1, 256>>>(nblk, N);
    scan_c_kernel<<<nblk, 512>>>(N);
    permute_kernel<<<(E + 255) / 256, 256>>>(eidx, E);
    edge_gather_kernel<<<592, 256>>>(rbf, coord, eidx, W1, b1, E, N);
    node_kernel<<<592, 256>>>(x, W2, b2, W3, b3, W4, b4, out, N);
}

// round 7
// speedup vs baseline: 1.8830x; 1.0568x over previous
#include <cuda_runtime.h>

// DimeNetBlock, round 7 (= round 6 resubmit; R6 was an infra failure).
// CSR gather with SMEM-staged features + packed f32x2 FMA + series angle.
// Pipeline: detect -> zero -> hist -> scan(a,b,c) -> permute
//           -> edge_gather -> node.

#define NNODE 100000
#define NEDGE 3200000
constexpr int EMB = 64;

typedef unsigned long long ull;

__device__ __align__(16) float g_S[(size_t)NNODE * 64];
__device__ int g_cnt[NNODE + 1];
__device__ int g_off[NNODE + 1];
__device__ int g_woff[NNODE];
__device__ int g_sorted[NEDGE];
__device__ int g_blk[256];
__device__ int g_blkoff[256];
__device__ int g_is64;

__device__ __forceinline__ float fsig(float x) {
    float e;
    asm("ex2.approx.f32 %0, %1;" : "=f"(e) : "f"(-1.4426950408889634f * x));
    float r;
    asm("rcp.approx.f32 %0, %1;" : "=f"(r) : "f"(1.0f + e));
    return r;
}

__device__ __forceinline__ ull pk2(float lo, float hi) {
    ull r; asm("mov.b64 %0, {%1, %2};" : "=l"(r) : "f"(lo), "f"(hi)); return r;
}
__device__ __forceinline__ float2 up2(ull v) {
    float2 f; asm("mov.b64 {%0, %1}, %2;" : "=f"(f.x), "=f"(f.y) : "l"(v)); return f;
}
__device__ __forceinline__ ull fma2(ull a, ull b, ull c) {
    ull d; asm("fma.rn.f32x2 %0, %1, %2, %3;" : "=l"(d) : "l"(a), "l"(b), "l"(c));
    return d;
}
__device__ __forceinline__ ull add2(ull a, ull b) {
    ull d; asm("add.rn.f32x2 %0, %1, %2;" : "=l"(d) : "l"(a), "l"(b)); return d;
}

__device__ __forceinline__ int load_row(const void* eidx_raw, int e, int is64) {
    if (is64) return (int)((const long long*)eidx_raw)[e];
    return ((const int*)eidx_raw)[e];
}

// ---------------------------------------------------------------------------
__global__ void detect_kernel(const long long* __restrict__ e64, int N) {
    bool ok = true;
#pragma unroll
    for (int i = 0; i < 8; i++) {
        long long v = e64[i];
        if (v < 0 || v >= (long long)N) ok = false;
    }
    g_is64 = ok ? 1 : 0;
}

__global__ void zero_cnt_kernel(int N) {
    int i = blockIdx.x * blockDim.x + threadIdx.x;
    if (i <= N) g_cnt[i] = 0;
}

__global__ void hist_kernel(const void* __restrict__ eidx_raw, int E) {
    int e = blockIdx.x * blockDim.x + threadIdx.x;
    if (e >= E) return;
    int r = load_row(eidx_raw, e, g_is64);
    atomicAdd(&g_cnt[r], 1);
}

// ---- scan: 512-wide chunks --------------------------------------------------
__global__ void scan_a_kernel(int N) {
    __shared__ int s[512];
    int i = blockIdx.x * 512 + threadIdx.x;
    s[threadIdx.x] = (i < N) ? g_cnt[i] : 0;
    __syncthreads();
    for (int d = 256; d > 0; d >>= 1) {
        if (threadIdx.x < d) s[threadIdx.x] += s[threadIdx.x + d];
        __syncthreads();
    }
    if (threadIdx.x == 0) g_blk[blockIdx.x] = s[0];
}

__global__ void scan_b_kernel(int nblk, int N) {
    __shared__ int sa[256], sb[256];
    int t = threadIdx.x;
    int v = (t < nblk) ? g_blk[t] : 0;
    sa[t] = v;
    __syncthreads();
    int* src = sa; int* dst = sb;
    for (int d = 1; d < 256; d <<= 1) {
        dst[t] = src[t] + ((t >= d) ? src[t - d] : 0);
        __syncthreads();
        int* tmp = src; src = dst; dst = tmp;
    }
    if (t < nblk) g_blkoff[t] = src[t] - v;
    if (t == nblk - 1) g_off[N] = src[t];
}

__global__ void scan_c_kernel(int N) {
    __shared__ int sa[512], sb[512];
    int t = threadIdx.x;
    int i = blockIdx.x * 512 + t;
    int v = (i < N) ? g_cnt[i] : 0;
    sa[t] = v;
    __syncthreads();
    int* src = sa; int* dst = sb;
    for (int d = 1; d < 512; d <<= 1) {
        dst[t] = src[t] + ((t >= d) ? src[t - d] : 0);
        __syncthreads();
        int* tmp = src; src = dst; dst = tmp;
    }
    if (i < N) {
        int off = g_blkoff[blockIdx.x] + src[t] - v;
        g_off[i]  = off;
        g_woff[i] = off;
    }
}

__global__ void permute_kernel(const void* __restrict__ eidx_raw, int E) {
    int e = blockIdx.x * blockDim.x + threadIdx.x;
    if (e >= E) return;
    int r = load_row(eidx_raw, e, g_is64);
    int p = atomicAdd(&g_woff[r], 1);
    g_sorted[p] = e;
}

// ---------------------------------------------------------------------------
// Edge gather, warp per node.
// Per 32-edge chunk: stage features [17 x 32] (stride 34, conflict-free) in
// per-warp SMEM; inner loop processes edge PAIRS: one LDS.64 per k gives
// (f_k(e0), f_k(e1)) feeding fma.rn.f32x2 against duplicated W1 columns.
// Angle: series pi - sqrt(2*delta)*(1+delta/12); acosf fallback for rare
// large-delta, pi/2 for the d<1e-24 norm-floor case.
// ---------------------------------------------------------------------------
__global__ void __launch_bounds__(256) edge_gather_kernel(
    const float* __restrict__ rbf, const float* __restrict__ coord,
    const void* __restrict__ eidx_raw,
    const float* __restrict__ W1, const float* __restrict__ b1, int E, int N)
{
    __shared__ __align__(16) float sfeat[8][17 * 34 + 2];
    __shared__ int is64s;
    if (threadIdx.x == 0) is64s = g_is64;
    __syncthreads();

    const int lane = threadIdx.x & 31;
    const int wid  = threadIdx.x >> 5;
    const int hv   = lane >> 4;
    const int k16  = lane & 15;
    const int i64  = is64s;
    float* sf = sfeat[wid];

    ull w1p0[17], w1p1[17];
#pragma unroll
    for (int k = 0; k < 17; k++) {
        float2 w = *(const float2*)&W1[k * 64 + 2 * lane];
        w1p0[k] = pk2(w.x, w.x);
        w1p1[k] = pk2(w.y, w.y);
    }
    float2 b1v = *(const float2*)&b1[2 * lane];

    const int*       c32 = (const int*)eidx_raw + E;
    const long long* c64 = (const long long*)eidx_raw + E;

    for (int n = blockIdx.x * 8 + wid; n < N; n += gridDim.x * 8) {
        int s0 = g_off[n], s1 = g_off[n + 1];
        float rx = coord[3 * n], ry = coord[3 * n + 1], rz = coord[3 * n + 2];
        ull acc0 = 0ull, acc1 = 0ull;

        for (int base = s0; base < s1; base += 32) {
            int m  = min(32, s1 - base);
            int np = (m + 1) >> 1;
            int eidv = g_sorted[min(base + lane, s1 - 1)];

            // ---- angle of edge (base+lane) ----
            int c = i64 ? (int)c64[eidv] : c32[eidv];
            float vx = rx - coord[3 * c];
            float vy = ry - coord[3 * c + 1];
            float vz = rz - coord[3 * c + 2];
            float d  = fmaf(vx, vx, fmaf(vy, vy, vz * vz));
            float angle;
            if (d >= 1e-24f) {
                float inv;
                asm("rsqrt.approx.f32 %0, %1;" : "=f"(inv) : "f"(d));
                float s = (d * inv) * inv;
                float delta = (s > 1.0f - 1e-8f) ? 1e-8f : (1.0f - s);
                if (delta < 1e-3f) {
                    float sq;
                    asm("sqrt.approx.f32 %0, %1;" : "=f"(sq) : "f"(2.0f * delta));
                    angle = 3.14159265358979f - sq * fmaf(delta, 0.08333333f, 1.0f);
                } else {               // rare: exact reference chain
                    float nrm = fmaxf(sqrtf(d), 1e-12f);
                    float ux = vx / nrm, uy = vy / nrm, uz = vz / nrm;
                    float sq2 = ux * ux + uy * uy + uz * uz;
                    float ca = fminf(fmaxf(-sq2, -1.0f + 1e-8f), 1.0f - 1e-8f);
                    angle = acosf(ca);
                }
            } else {                   // ||v|| under norm floor: acos(-0)=pi/2
                angle = 1.5707963267948966f;
            }
            sf[16 * 34 + lane] = angle;

            // ---- stage rbf features: row k16, edges 2r+hv ----
            for (int r = 0; r < np; r++) {
                int es = __shfl_sync(0xffffffffu, eidv, 2 * r + hv);
                sf[k16 * 34 + 2 * r + hv] = rbf[(size_t)es * 16 + k16];
            }
            __syncwarp();

            for (int p = 0; p < np; p++) {
                ull h0 = pk2(b1v.x, b1v.x);
                ull h1 = pk2(b1v.y, b1v.y);
#pragma unroll
                for (int k = 0; k < 17; k++) {
                    ull f = *(const ull*)&sf[k * 34 + 2 * p];
                    h0 = fma2(f, w1p0[k], h0);
                    h1 = fma2(f, w1p1[k], h1);
                }
                float2 u0 = up2(h0), u1 = up2(h1);
                float s00 = u0.x * fsig(u0.x);
                float s01 = u0.y * fsig(u0.y);
                float s10 = u1.x * fsig(u1.x);
                float s11 = u1.y * fsig(u1.y);
                if (2 * p + 1 < m) {
                    acc0 = add2(acc0, pk2(s00, s01));
                    acc1 = add2(acc1, pk2(s10, s11));
                } else {
                    acc0 = add2(acc0, pk2(s00, 0.0f));
                    acc1 = add2(acc1, pk2(s10, 0.0f));
                }
            }
            __syncwarp();
        }
        float2 a0 = up2(acc0), a1 = up2(acc1);
        *(float2*)&g_S[(size_t)n * 64 + 2 * lane] =
            make_float2(a0.x + a0.y, a1.x + a1.y);
    }
}

// ---------------------------------------------------------------------------
// Node kernel: warp processes 8 nodes; 48KB weights in SMEM.
// ---------------------------------------------------------------------------
__global__ void __launch_bounds__(256) node_kernel(
    const float* __restrict__ x,
    const float* __restrict__ W2, const float* __restrict__ b2,
    const float* __restrict__ W3, const float* __restrict__ b3,
    const float* __restrict__ W4, const float* __restrict__ b4,
    float* __restrict__ out, int N)
{
    __shared__ __align__(16) float Ws[3 * 64 * 64];
    for (int i = threadIdx.x; i < 4096; i += 256) {
        Ws[i]        = W2[i];
        Ws[4096 + i] = W3[i];
        Ws[8192 + i] = W4[i];
    }
    __syncthreads();

    int lane = threadIdx.x & 31;
    int wid  = threadIdx.x >> 5;
    float2 bb2 = *(const float2*)&b2[2 * lane];
    float2 bb3 = *(const float2*)&b3[2 * lane];
    float2 bb4 = *(const float2*)&b4[2 * lane];

    for (int g = blockIdx.x * 8 + wid; g * 8 < N; g += gridDim.x * 8) {
        int n0 = g * 8;
        float2 v[8];
        float  dg[8];
#pragma unroll
        for (int t = 0; t < 8; t++) {
            int n = n0 + t;
            if (n < N) {
                v[t]  = *(const float2*)&g_S[(size_t)n * 64 + 2 * lane];
                dg[t] = (float)(g_off[n + 1] - g_off[n]);
            } else {
                v[t] = make_float2(0.f, 0.f); dg[t] = 0.f;
            }
        }

        float2 a[8];
#pragma unroll
        for (int t = 0; t < 8; t++)
            a[t] = make_float2(dg[t] * bb2.x, dg[t] * bb2.y);

#pragma unroll 4
        for (int kk = 0; kk < 32; kk++) {
            float2 w0 = *(const float2*)&Ws[(2 * kk)     * 64 + 2 * lane];
            float2 w1 = *(const float2*)&Ws[(2 * kk + 1) * 64 + 2 * lane];
#pragma unroll
            for (int t = 0; t < 8; t++) {
                float x0 = __shfl_sync(0xffffffffu, v[t].x, kk);
                float x1 = __shfl_sync(0xffffffffu, v[t].y, kk);
                a[t].x = fmaf(x0, w0.x, fmaf(x1, w1.x, a[t].x));
                a[t].y = fmaf(x0, w0.y, fmaf(x1, w1.y, a[t].y));
            }
        }

        float2 p[8];
#pragma unroll
        for (int t = 0; t < 8; t++) p[t] = bb3;
#pragma unroll 4
        for (int kk = 0; kk < 32; kk++) {
            float2 w0 = *(const float2*)&Ws[4096 + (2 * kk)     * 64 + 2 * lane];
            float2 w1 = *(const float2*)&Ws[4096 + (2 * kk + 1) * 64 + 2 * lane];
#pragma unroll
            for (int t = 0; t < 8; t++) {
                float x0 = __shfl_sync(0xffffffffu, a[t].x, kk);
                float x1 = __shfl_sync(0xffffffffu, a[t].y, kk);
                p[t].x = fmaf(x0, w0.x, fmaf(x1, w1.x, p[t].x));
                p[t].y = fmaf(x0, w0.y, fmaf(x1, w1.y, p[t].y));
            }
        }
#pragma unroll
        for (int t = 0; t < 8; t++) {
            p[t].x *= fsig(p[t].x);
            p[t].y *= fsig(p[t].y);
        }

        float2 q[8];
#pragma unroll
        for (int t = 0; t < 8; t++) q[t] = bb4;
#pragma unroll 4
        for (int kk = 0; kk < 32; kk++) {
            float2 w0 = *(const float2*)&Ws[8192 + (2 * kk)     * 64 + 2 * lane];
            float2 w1 = *(const float2*)&Ws[8192 + (2 * kk + 1) * 64 + 2 * lane];
#pragma unroll
            for (int t = 0; t < 8; t++) {
                float x0 = __shfl_sync(0xffffffffu, p[t].x, kk);
                float x1 = __shfl_sync(0xffffffffu, p[t].y, kk);
                q[t].x = fmaf(x0, w0.x, fmaf(x1, w1.x, q[t].x));
                q[t].y = fmaf(x0, w0.y, fmaf(x1, w1.y, q[t].y));
            }
        }
#pragma unroll
        for (int t = 0; t < 8; t++) {
            int n = n0 + t;
            if (n < N) {
                float2 xv = *(const float2*)&x[(size_t)n * 64 + 2 * lane];
                *(float2*)&out[(size_t)n * 64 + 2 * lane] =
                    make_float2(xv.x + q[t].x, xv.y + q[t].y);
            }
        }
    }
}

// ---------------------------------------------------------------------------
extern "C" void kernel_launch(void* const* d_in, const int* in_sizes, int n_in,
                              void* d_out, int out_size)
{
    const float* x     = (const float*)d_in[0];
    const float* coord = (const float*)d_in[1];
    const float* rbf   = (const float*)d_in[2];
    const void*  eidx  = d_in[3];
    const float* W1 = (const float*)d_in[4];
    const float* b1 = (const float*)d_in[5];
    const float* W2 = (const float*)d_in[6];
    const float* b2 = (const float*)d_in[7];
    const float* W3 = (const float*)d_in[8];
    const float* b3 = (const float*)d_in[9];
    const float* W4 = (const float*)d_in[10];
    const float* b4 = (const float*)d_in[11];
    float* out = (float*)d_out;

    int E = in_sizes[3] / 2;
    int N = in_sizes[0] / EMB;
    int nblk = (N + 511) / 512;

    detect_kernel<<<1, 1>>>((const long long*)eidx, N);
    zero_cnt_kernel<<<(N + 256) / 256, 256>>>(N);
    hist_kernel<<<(E + 255) / 256, 256>>>(eidx, E);
    scan_a_kernel<<<nblk, 512>>>(N);
    scan_b_kernel<<<1, 256>>>(nblk, N);
    scan_c_kernel<<<nblk, 512>>>(N);
    permute_kernel<<<(E + 255) / 256, 256>>>(eidx, E);
    edge_gather_kernel<<<592, 256>>>(rbf, coord, eidx, W1, b1, E, N);
    node_kernel<<<592, 256>>>(x, W2, b2, W3, b3, W4, b4, out, N);
}

// round 8
// speedup vs baseline: 2.0447x; 1.0859x over previous
#include <cuda_runtime.h>

// DimeNetBlock, round 8: angle folded to constant (self-loops flagged in
// g_sorted top bit during permute), edge kernel reads ONLY g_sorted + rbf,
// 64-edge staging waves. CSR pipeline otherwise as R7.

#define NNODE 100000
#define NEDGE 3200000
constexpr int EMB = 64;

typedef unsigned long long ull;

__device__ __align__(16) float g_S[(size_t)NNODE * 64];
__device__ int g_cnt[NNODE + 1];
__device__ int g_off[NNODE + 1];
__device__ int g_woff[NNODE];
__device__ int g_sorted[NEDGE];
__device__ int g_blk[256];
__device__ int g_blkoff[256];
__device__ int g_is64;

__device__ __forceinline__ float fsig(float x) {
    float e;
    asm("ex2.approx.f32 %0, %1;" : "=f"(e) : "f"(-1.4426950408889634f * x));
    float r;
    asm("rcp.approx.f32 %0, %1;" : "=f"(r) : "f"(1.0f + e));
    return r;
}

__device__ __forceinline__ ull pk2(float lo, float hi) {
    ull r; asm("mov.b64 %0, {%1, %2};" : "=l"(r) : "f"(lo), "f"(hi)); return r;
}
__device__ __forceinline__ float2 up2(ull v) {
    float2 f; asm("mov.b64 {%0, %1}, %2;" : "=f"(f.x), "=f"(f.y) : "l"(v)); return f;
}
__device__ __forceinline__ ull fma2(ull a, ull b, ull c) {
    ull d; asm("fma.rn.f32x2 %0, %1, %2, %3;" : "=l"(d) : "l"(a), "l"(b), "l"(c));
    return d;
}
__device__ __forceinline__ ull add2(ull a, ull b) {
    ull d; asm("add.rn.f32x2 %0, %1, %2;" : "=l"(d) : "l"(a), "l"(b)); return d;
}

__device__ __forceinline__ int load_row(const void* eidx_raw, int e, int is64) {
    if (is64) return (int)((const long long*)eidx_raw)[e];
    return ((const int*)eidx_raw)[e];
}

// ---------------------------------------------------------------------------
__global__ void detect_kernel(const long long* __restrict__ e64, int N) {
    bool ok = true;
#pragma unroll
    for (int i = 0; i < 8; i++) {
        long long v = e64[i];
        if (v < 0 || v >= (long long)N) ok = false;
    }
    g_is64 = ok ? 1 : 0;
}

__global__ void zero_cnt_kernel(int N) {
    int i = blockIdx.x * blockDim.x + threadIdx.x;
    if (i <= N) g_cnt[i] = 0;
}

__global__ void hist_kernel(const void* __restrict__ eidx_raw, int E) {
    int e = blockIdx.x * blockDim.x + threadIdx.x;
    if (e >= E) return;
    int r = load_row(eidx_raw, e, g_is64);
    atomicAdd(&g_cnt[r], 1);
}

// ---- scan: 512-wide chunks --------------------------------------------------
__global__ void scan_a_kernel(int N) {
    __shared__ int s[512];
    int i = blockIdx.x * 512 + threadIdx.x;
    s[threadIdx.x] = (i < N) ? g_cnt[i] : 0;
    __syncthreads();
    for (int d = 256; d > 0; d >>= 1) {
        if (threadIdx.x < d) s[threadIdx.x] += s[threadIdx.x + d];
        __syncthreads();
    }
    if (threadIdx.x == 0) g_blk[blockIdx.x] = s[0];
}

__global__ void scan_b_kernel(int nblk, int N) {
    __shared__ int sa[256], sb[256];
    int t = threadIdx.x;
    int v = (t < nblk) ? g_blk[t] : 0;
    sa[t] = v;
    __syncthreads();
    int* src = sa; int* dst = sb;
    for (int d = 1; d < 256; d <<= 1) {
        dst[t] = src[t] + ((t >= d) ? src[t - d] : 0);
        __syncthreads();
        int* tmp = src; src = dst; dst = tmp;
    }
    if (t < nblk) g_blkoff[t] = src[t] - v;
    if (t == nblk - 1) g_off[N] = src[t];
}

__global__ void scan_c_kernel(int N) {
    __shared__ int sa[512], sb[512];
    int t = threadIdx.x;
    int i = blockIdx.x * 512 + t;
    int v = (i < N) ? g_cnt[i] : 0;
    sa[t] = v;
    __syncthreads();
    int* src = sa; int* dst = sb;
    for (int d = 1; d < 512; d <<= 1) {
        dst[t] = src[t] + ((t >= d) ? src[t - d] : 0);
        __syncthreads();
        int* tmp = src; src = dst; dst = tmp;
    }
    if (i < N) {
        int off = g_blkoff[blockIdx.x] + src[t] - v;
        g_off[i]  = off;
        g_woff[i] = off;
    }
}

// permute: also reads col (coalesced here) and flags self-loops in top bit.
__global__ void permute_kernel(const void* __restrict__ eidx_raw, int E) {
    int e = blockIdx.x * blockDim.x + threadIdx.x;
    if (e >= E) return;
    int r = load_row(eidx_raw, e, g_is64);
    int c = load_row(eidx_raw, E + e, g_is64);
    int p = atomicAdd(&g_woff[r], 1);
    g_sorted[p] = e | ((r == c) ? (int)0x80000000 : 0);
}

// ---------------------------------------------------------------------------
// Edge gather, warp per node, NO coord/angle work:
//   h_e = silu(rbf_e @ W1[0:16] + b1 + A*W1[16])   (+ (pi/2-A)*W1[16] if self-loop)
// 64 edges staged per wave (feature tile 16 x 64, stride 66, conflict-free),
// pairs of edges packed into fma.rn.f32x2 against duplicated W1 columns.
// ---------------------------------------------------------------------------
#define ANG_A 3.14129265f            /* pi - 3e-4: constant angle */
#define ANG_CORR (1.57079633f - ANG_A)

struct EdgeCtx {
    ull w1p0[16], w1p1[16];
    ull b0p, b1p, wc0, wc1;
};

__device__ __forceinline__ void do_chunk(
    const float* __restrict__ sf, int coloff, int mm, unsigned slmask,
    const EdgeCtx& C, ull& acc0, ull& acc1)
{
    int np = (mm + 1) >> 1;
    for (int p = 0; p < np; p++) {
        ull h0 = C.b0p, h1 = C.b1p;
#pragma unroll
        for (int k = 0; k < 16; k++) {
            ull f = *(const ull*)&sf[k * 66 + coloff + 2 * p];
            h0 = fma2(f, C.w1p0[k], h0);
            h1 = fma2(f, C.w1p1[k], h1);
        }
        if (slmask) {                       // self-loop correction (rare)
            float c0 = ((slmask >> (2 * p)) & 1u) ? ANG_CORR : 0.f;
            float c1 = ((slmask >> (2 * p + 1)) & 1u) ? ANG_CORR : 0.f;
            ull cp = pk2(c0, c1);
            h0 = fma2(cp, C.wc0, h0);
            h1 = fma2(cp, C.wc1, h1);
        }
        float2 u0 = up2(h0), u1 = up2(h1);
        float s00 = u0.x * fsig(u0.x);
        float s01 = u0.y * fsig(u0.y);
        float s10 = u1.x * fsig(u1.x);
        float s11 = u1.y * fsig(u1.y);
        bool full = (2 * p + 1 < mm);
        acc0 = add2(acc0, pk2(s00, full ? s01 : 0.f));
        acc1 = add2(acc1, pk2(s10, full ? s11 : 0.f));
    }
}

__global__ void __launch_bounds__(256) edge_gather_kernel(
    const float* __restrict__ rbf,
    const float* __restrict__ W1, const float* __restrict__ b1, int N)
{
    __shared__ __align__(16) float sfeat[8][16 * 66];
    const int lane = threadIdx.x & 31;
    const int wid  = threadIdx.x >> 5;
    const int hv   = lane >> 4;
    const int k16  = lane & 15;
    float* sf = sfeat[wid];

    EdgeCtx C;
#pragma unroll
    for (int k = 0; k < 16; k++) {
        float2 w = *(const float2*)&W1[k * 64 + 2 * lane];
        C.w1p0[k] = pk2(w.x, w.x);
        C.w1p1[k] = pk2(w.y, w.y);
    }
    {
        float2 w16 = *(const float2*)&W1[16 * 64 + 2 * lane];
        float2 bv  = *(const float2*)&b1[2 * lane];
        float bx = fmaf(ANG_A, w16.x, bv.x);
        float by = fmaf(ANG_A, w16.y, bv.y);
        C.b0p = pk2(bx, bx);
        C.b1p = pk2(by, by);
        C.wc0 = pk2(w16.x, w16.x);
        C.wc1 = pk2(w16.y, w16.y);
    }

    for (int n = blockIdx.x * 8 + wid; n < N; n += gridDim.x * 8) {
        int s0 = g_off[n], s1 = g_off[n + 1];
        ull acc0 = 0ull, acc1 = 0ull;

        for (int base = s0; base < s1; base += 64) {
            int m  = min(64, s1 - base);
            int mA = min(m, 32), mB = m - mA;
            int eA = g_sorted[min(base + lane, s1 - 1)];
            int eB = g_sorted[min(base + 32 + lane, s1 - 1)];
            unsigned slA = __ballot_sync(0xffffffffu, eA < 0);
            unsigned slB = __ballot_sync(0xffffffffu, eB < 0);
            int npA = (mA + 1) >> 1, npB = (mB + 1) >> 1;

            for (int r = 0; r < npA; r++) {
                int es = __shfl_sync(0xffffffffu, eA, 2 * r + hv) & 0x7fffffff;
                sf[k16 * 66 + 2 * r + hv] = rbf[(size_t)es * 16 + k16];
            }
            for (int r = 0; r < npB; r++) {
                int es = __shfl_sync(0xffffffffu, eB, 2 * r + hv) & 0x7fffffff;
                sf[k16 * 66 + 32 + 2 * r + hv] = rbf[(size_t)es * 16 + k16];
            }
            __syncwarp();

            do_chunk(sf, 0, mA, slA, C, acc0, acc1);
            if (mB > 0) do_chunk(sf, 32, mB, slB, C, acc0, acc1);
            __syncwarp();
        }
        float2 a0 = up2(acc0), a1 = up2(acc1);
        *(float2*)&g_S[(size_t)n * 64 + 2 * lane] =
            make_float2(a0.x + a0.y, a1.x + a1.y);
    }
}

// ---------------------------------------------------------------------------
// Node kernel: warp processes 8 nodes; 48KB weights in SMEM (as R7).
// ---------------------------------------------------------------------------
__global__ void __launch_bounds__(256) node_kernel(
    const float* __restrict__ x,
    const float* __restrict__ W2, const float* __restrict__ b2,
    const float* __restrict__ W3, const float* __restrict__ b3,
    const float* __restrict__ W4, const float* __restrict__ b4,
    float* __restrict__ out, int N)
{
    __shared__ __align__(16) float Ws[3 * 64 * 64];
    for (int i = threadIdx.x; i < 4096; i += 256) {
        Ws[i]        = W2[i];
        Ws[4096 + i] = W3[i];
        Ws[8192 + i] = W4[i];
    }
    __syncthreads();

    int lane = threadIdx.x & 31;
    int wid  = threadIdx.x >> 5;
    float2 bb2 = *(const float2*)&b2[2 * lane];
    float2 bb3 = *(const float2*)&b3[2 * lane];
    float2 bb4 = *(const float2*)&b4[2 * lane];

    for (int g = blockIdx.x * 8 + wid; g * 8 < N; g += gridDim.x * 8) {
        int n0 = g * 8;
        float2 v[8];
        float  dg[8];
#pragma unroll
        for (int t = 0; t < 8; t++) {
            int n = n0 + t;
            if (n < N) {
                v[t]  = *(const float2*)&g_S[(size_t)n * 64 + 2 * lane];
                dg[t] = (float)(g_off[n + 1] - g_off[n]);
            } else {
                v[t] = make_float2(0.f, 0.f); dg[t] = 0.f;
            }
        }

        float2 a[8];
#pragma unroll
        for (int t = 0; t < 8; t++)
            a[t] = make_float2(dg[t] * bb2.x, dg[t] * bb2.y);

#pragma unroll 4
        for (int kk = 0; kk < 32; kk++) {
            float2 w0 = *(const float2*)&Ws[(2 * kk)     * 64 + 2 * lane];
            float2 w1 = *(const float2*)&Ws[(2 * kk + 1) * 64 + 2 * lane];
#pragma unroll
            for (int t = 0; t < 8; t++) {
                float x0 = __shfl_sync(0xffffffffu, v[t].x, kk);
                float x1 = __shfl_sync(0xffffffffu, v[t].y, kk);
                a[t].x = fmaf(x0, w0.x, fmaf(x1, w1.x, a[t].x));
                a[t].y = fmaf(x0, w0.y, fmaf(x1, w1.y, a[t].y));
            }
        }

        float2 p[8];
#pragma unroll
        for (int t = 0; t < 8; t++) p[t] = bb3;
#pragma unroll 4
        for (int kk = 0; kk < 32; kk++) {
            float2 w0 = *(const float2*)&Ws[4096 + (2 * kk)     * 64 + 2 * lane];
            float2 w1 = *(const float2*)&Ws[4096 + (2 * kk + 1) * 64 + 2 * lane];
#pragma unroll
            for (int t = 0; t < 8; t++) {
                float x0 = __shfl_sync(0xffffffffu, a[t].x, kk);
                float x1 = __shfl_sync(0xffffffffu, a[t].y, kk);
                p[t].x = fmaf(x0, w0.x, fmaf(x1, w1.x, p[t].x));
                p[t].y = fmaf(x0, w0.y, fmaf(x1, w1.y, p[t].y));
            }
        }
#pragma unroll
        for (int t = 0; t < 8; t++) {
            p[t].x *= fsig(p[t].x);
            p[t].y *= fsig(p[t].y);
        }

        float2 q[8];
#pragma unroll
        for (int t = 0; t < 8; t++) q[t] = bb4;
#pragma unroll 4
        for (int kk = 0; kk < 32; kk++) {
            float2 w0 = *(const float2*)&Ws[8192 + (2 * kk)     * 64 + 2 * lane];
            float2 w1 = *(const float2*)&Ws[8192 + (2 * kk + 1) * 64 + 2 * lane];
#pragma unroll
            for (int t = 0; t < 8; t++) {
                float x0 = __shfl_sync(0xffffffffu, p[t].x, kk);
                float x1 = __shfl_sync(0xffffffffu, p[t].y, kk);
                q[t].x = fmaf(x0, w0.x, fmaf(x1, w1.x, q[t].x));
                q[t].y = fmaf(x0, w0.y, fmaf(x1, w1.y, q[t].y));
            }
        }
#pragma unroll
        for (int t = 0; t < 8; t++) {
            int n = n0 + t;
            if (n < N) {
                float2 xv = *(const float2*)&x[(size_t)n * 64 + 2 * lane];
                *(float2*)&out[(size_t)n * 64 + 2 * lane] =
                    make_float2(xv.x + q[t].x, xv.y + q[t].y);
            }
        }
    }
}

// ---------------------------------------------------------------------------
extern "C" void kernel_launch(void* const* d_in, const int* in_sizes, int n_in,
                              void* d_out, int out_size)
{
    const float* x     = (const float*)d_in[0];
    const float* rbf   = (const float*)d_in[2];
    const void*  eidx  = d_in[3];
    const float* W1 = (const float*)d_in[4];
    const float* b1 = (const float*)d_in[5];
    const float* W2 = (const float*)d_in[6];
    const float* b2 = (const float*)d_in[7];
    const float* W3 = (const float*)d_in[8];
    const float* b3 = (const float*)d_in[9];
    const float* W4 = (const float*)d_in[10];
    const float* b4 = (const float*)d_in[11];
    float* out = (float*)d_out;

    int E = in_sizes[3] / 2;
    int N = in_sizes[0] / EMB;
    int nblk = (N + 511) / 512;

    detect_kernel<<<1, 1>>>((const long long*)eidx, N);
    zero_cnt_kernel<<<(N + 256) / 256, 256>>>(N);
    hist_kernel<<<(E + 255) / 256, 256>>>(eidx, E);
    scan_a_kernel<<<nblk, 512>>>(N);
    scan_b_kernel<<<1, 256>>>(nblk, N);
    scan_c_kernel<<<nblk, 512>>>(N);
    permute_kernel<<<(E + 255) / 256, 256>>>(eidx, E);
    edge_gather_kernel<<<592, 256>>>(rbf, W1, b1, N);
    node_kernel<<<592, 256>>>(x, W2, b2, W3, b3, W4, b4, out, N);
}

// round 10
// speedup vs baseline: 2.8610x; 1.3992x over previous
#include <cuda_runtime.h>

// DimeNetBlock, round 10 (= round 9 resubmit; R9 was an infra failure).
// 5-launch pipeline (hist, lookback-scan, permute, edge_gather, node).
// int32 indices hardcoded. Scan consumes+resets g_cnt; permute resets
// lookback flags -> no zero kernel. Edge: float4 staging, tanh-based silu
// (1 MUFU), constant-angle fold with self-loop correction.

#define NNODE 100000
#define NEDGE 3200000
constexpr int EMB = 64;

typedef unsigned long long ull;

__device__ __align__(16) float g_S[(size_t)NNODE * 64];
__device__ int g_cnt[NNODE + 512];
__device__ int g_off[NNODE + 1];
__device__ int g_woff[NNODE];
__device__ int g_sorted[NEDGE];
__device__ unsigned int g_scanblk[256];

__device__ __forceinline__ float fsig(float x) {
    float e;
    asm("ex2.approx.f32 %0, %1;" : "=f"(e) : "f"(-1.4426950408889634f * x));
    float r;
    asm("rcp.approx.f32 %0, %1;" : "=f"(r) : "f"(1.0f + e));
    return r;
}
__device__ __forceinline__ float fsilu_tanh(float x) {
    float h = 0.5f * x, t;
    asm("tanh.approx.f32 %0, %1;" : "=f"(t) : "f"(h));
    return fmaf(h, t, h);
}

__device__ __forceinline__ ull pk2(float lo, float hi) {
    ull r; asm("mov.b64 %0, {%1, %2};" : "=l"(r) : "f"(lo), "f"(hi)); return r;
}
__device__ __forceinline__ float2 up2(ull v) {
    float2 f; asm("mov.b64 {%0, %1}, %2;" : "=f"(f.x), "=f"(f.y) : "l"(v)); return f;
}
__device__ __forceinline__ ull fma2(ull a, ull b, ull c) {
    ull d; asm("fma.rn.f32x2 %0, %1, %2, %3;" : "=l"(d) : "l"(a), "l"(b), "l"(c));
    return d;
}
__device__ __forceinline__ ull add2(ull a, ull b) {
    ull d; asm("add.rn.f32x2 %0, %1, %2;" : "=l"(d) : "l"(a), "l"(b)); return d;
}

// ---------------------------------------------------------------------------
// 1) histogram of row indices (g_cnt starts zero: zero-init run 1, reset by
//    scan_kernel every replay).
// ---------------------------------------------------------------------------
__global__ void hist_kernel(const int* __restrict__ eidx, int E) {
    int e = blockIdx.x * blockDim.x + threadIdx.x;
    if (e >= E) return;
    atomicAdd(&g_cnt[eidx[e]], 1);
}

// ---------------------------------------------------------------------------
// 2) decoupled-lookback exclusive scan; also zeroes g_cnt for next replay.
//    g_scanblk flags start zero (zero-init run 1, reset by permute_kernel).
//    Flag and value share one 32-bit word -> no fence needed.
// ---------------------------------------------------------------------------
__global__ void __launch_bounds__(512) scan_kernel(int N, int E) {
    __shared__ int s[512];
    __shared__ int blk_prefix;
    int b = blockIdx.x, t = threadIdx.x;
    int i = b * 512 + t;
    int v = (i < N) ? g_cnt[i] : 0;
    if (i < N) g_cnt[i] = 0;
    s[t] = v;
    __syncthreads();
    for (int d = 1; d < 512; d <<= 1) {
        int add = (t >= d) ? s[t - d] : 0;
        __syncthreads();
        s[t] += add;
        __syncthreads();
    }
    int incl = s[t];
    if (t == 0) {
        unsigned total = (unsigned)s[511];
        volatile unsigned* vb = g_scanblk;
        if (b == 0) {
            vb[0] = total | 0x80000000u;      // status 2 (inclusive)
            blk_prefix = 0;
        } else {
            vb[b] = total | 0x40000000u;      // status 1 (aggregate)
            unsigned run = 0;
            int p = b - 1;
            while (true) {
                unsigned f = vb[p];
                unsigned st = f >> 30;
                if (st == 0u) continue;
                run += f & 0x3FFFFFFFu;
                if (st >= 2u) break;
                p--;
            }
            vb[b] = (run + total) | 0x80000000u;
            blk_prefix = (int)run;
        }
    }
    __syncthreads();
    int ex = blk_prefix + incl - v;
    if (i < N) {
        g_off[i]  = ex;
        g_woff[i] = ex;
        if (i == N - 1) g_off[N] = ex + v;
    }
}

// ---------------------------------------------------------------------------
// 3) permute: scatter edge ids into row-sorted order; flag self-loops in the
//    top bit; block 0 resets the lookback flags for the next replay.
// ---------------------------------------------------------------------------
__global__ void permute_kernel(const int* __restrict__ eidx, int E) {
    if (blockIdx.x == 0 && threadIdx.x < 256) g_scanblk[threadIdx.x] = 0u;
    int e = blockIdx.x * blockDim.x + threadIdx.x;
    if (e >= E) return;
    int r = eidx[e];
    int c = eidx[(size_t)E + e];
    int p = atomicAdd(&g_woff[r], 1);
    g_sorted[p] = e | ((r == c) ? (int)0x80000000 : 0);
}

// ---------------------------------------------------------------------------
// 4) edge gather (warp per node): h_e = silu(rbf_e @ W1[0:16] + b1 + A*W1[16])
//    + rare self-loop correction. float4 staging (8 edges / iteration).
// ---------------------------------------------------------------------------
#define ANG_A 3.14129265f            /* pi - 3e-4: constant angle */
#define ANG_CORR (1.57079633f - ANG_A)

struct EdgeCtx {
    ull w1p0[16], w1p1[16];
    ull b0p, b1p, wc0, wc1;
};

__device__ __forceinline__ void do_chunk(
    const float* __restrict__ sf, int coloff, int mm, unsigned slmask,
    const EdgeCtx& C, ull& acc0, ull& acc1)
{
    int np = (mm + 1) >> 1;
    for (int p = 0; p < np; p++) {
        ull h0 = C.b0p, h1 = C.b1p;
#pragma unroll
        for (int k = 0; k < 16; k++) {
            ull f = *(const ull*)&sf[k * 66 + coloff + 2 * p];
            h0 = fma2(f, C.w1p0[k], h0);
            h1 = fma2(f, C.w1p1[k], h1);
        }
        if (slmask) {
            float c0 = ((slmask >> (2 * p)) & 1u) ? ANG_CORR : 0.f;
            float c1 = ((slmask >> (2 * p + 1)) & 1u) ? ANG_CORR : 0.f;
            ull cp = pk2(c0, c1);
            h0 = fma2(cp, C.wc0, h0);
            h1 = fma2(cp, C.wc1, h1);
        }
        float2 u0 = up2(h0), u1 = up2(h1);
        float s00 = fsilu_tanh(u0.x);
        float s01 = fsilu_tanh(u0.y);
        float s10 = fsilu_tanh(u1.x);
        float s11 = fsilu_tanh(u1.y);
        bool full = (2 * p + 1 < mm);
        acc0 = add2(acc0, pk2(s00, full ? s01 : 0.f));
        acc1 = add2(acc1, pk2(s10, full ? s11 : 0.f));
    }
}

__global__ void __launch_bounds__(256) edge_gather_kernel(
    const float* __restrict__ rbf,
    const float* __restrict__ W1, const float* __restrict__ b1, int N)
{
    __shared__ __align__(16) float sfeat[8][16 * 66];
    const int lane = threadIdx.x & 31;
    const int wid  = threadIdx.x >> 5;
    const int sub8 = lane >> 2;          // 0..7 : edge within 8-edge group
    const int cmp4 = lane & 3;           // 0..3 : float4 component group
    float* sf = sfeat[wid];

    EdgeCtx C;
#pragma unroll
    for (int k = 0; k < 16; k++) {
        float2 w = *(const float2*)&W1[k * 64 + 2 * lane];
        C.w1p0[k] = pk2(w.x, w.x);
        C.w1p1[k] = pk2(w.y, w.y);
    }
    {
        float2 w16 = *(const float2*)&W1[16 * 64 + 2 * lane];
        float2 bv  = *(const float2*)&b1[2 * lane];
        float bx = fmaf(ANG_A, w16.x, bv.x);
        float by = fmaf(ANG_A, w16.y, bv.y);
        C.b0p = pk2(bx, bx);
        C.b1p = pk2(by, by);
        C.wc0 = pk2(w16.x, w16.x);
        C.wc1 = pk2(w16.y, w16.y);
    }

    for (int n = blockIdx.x * 8 + wid; n < N; n += gridDim.x * 8) {
        int s0 = g_off[n], s1 = g_off[n + 1];
        ull acc0 = 0ull, acc1 = 0ull;

        for (int base = s0; base < s1; base += 64) {
            int m  = min(64, s1 - base);
            int mA = min(m, 32), mB = m - mA;
            int eA = g_sorted[min(base + lane, s1 - 1)];
            int eB = g_sorted[min(base + 32 + lane, s1 - 1)];
            unsigned slA = __ballot_sync(0xffffffffu, eA < 0);
            unsigned slB = __ballot_sync(0xffffffffu, eB < 0);
            int itA = (mA + 7) >> 3, itB = (mB + 7) >> 3;

            for (int r = 0; r < itA; r++) {
                int col = r * 8 + sub8;
                int es = __shfl_sync(0xffffffffu, eA, col) & 0x7fffffff;
                float4 f4 = *(const float4*)&rbf[(size_t)es * 16 + 4 * cmp4];
                sf[(4 * cmp4 + 0) * 66 + col] = f4.x;
                sf[(4 * cmp4 + 1) * 66 + col] = f4.y;
                sf[(4 * cmp4 + 2) * 66 + col] = f4.z;
                sf[(4 * cmp4 + 3) * 66 + col] = f4.w;
            }
            for (int r = 0; r < itB; r++) {
                int col = r * 8 + sub8;
                int es = __shfl_sync(0xffffffffu, eB, col) & 0x7fffffff;
                float4 f4 = *(const float4*)&rbf[(size_t)es * 16 + 4 * cmp4];
                sf[(4 * cmp4 + 0) * 66 + 32 + col] = f4.x;
                sf[(4 * cmp4 + 1) * 66 + 32 + col] = f4.y;
                sf[(4 * cmp4 + 2) * 66 + 32 + col] = f4.z;
                sf[(4 * cmp4 + 3) * 66 + 32 + col] = f4.w;
            }
            __syncwarp();

            do_chunk(sf, 0, mA, slA, C, acc0, acc1);
            if (mB > 0) do_chunk(sf, 32, mB, slB, C, acc0, acc1);
            __syncwarp();
        }
        float2 a0 = up2(acc0), a1 = up2(acc1);
        *(float2*)&g_S[(size_t)n * 64 + 2 * lane] =
            make_float2(a0.x + a0.y, a1.x + a1.y);
    }
}

// ---------------------------------------------------------------------------
// 5) node: warp processes 8 nodes; 48KB weights in SMEM.
// ---------------------------------------------------------------------------
__global__ void __launch_bounds__(256) node_kernel(
    const float* __restrict__ x,
    const float* __restrict__ W2, const float* __restrict__ b2,
    const float* __restrict__ W3, const float* __restrict__ b3,
    const float* __restrict__ W4, const float* __restrict__ b4,
    float* __restrict__ out, int N)
{
    __shared__ __align__(16) float Ws[3 * 64 * 64];
    for (int i = threadIdx.x; i < 4096; i += 256) {
        Ws[i]        = W2[i];
        Ws[4096 + i] = W3[i];
        Ws[8192 + i] = W4[i];
    }
    __syncthreads();

    int lane = threadIdx.x & 31;
    int wid  = threadIdx.x >> 5;
    float2 bb2 = *(const float2*)&b2[2 * lane];
    float2 bb3 = *(const float2*)&b3[2 * lane];
    float2 bb4 = *(const float2*)&b4[2 * lane];

    for (int g = blockIdx.x * 8 + wid; g * 8 < N; g += gridDim.x * 8) {
        int n0 = g * 8;
        float2 v[8];
        float  dg[8];
#pragma unroll
        for (int t = 0; t < 8; t++) {
            int n = n0 + t;
            if (n < N) {
                v[t]  = *(const float2*)&g_S[(size_t)n * 64 + 2 * lane];
                dg[t] = (float)(g_off[n + 1] - g_off[n]);
            } else {
                v[t] = make_float2(0.f, 0.f); dg[t] = 0.f;
            }
        }

        float2 a[8];
#pragma unroll
        for (int t = 0; t < 8; t++)
            a[t] = make_float2(dg[t] * bb2.x, dg[t] * bb2.y);

#pragma unroll 4
        for (int kk = 0; kk < 32; kk++) {
            float2 w0 = *(const float2*)&Ws[(2 * kk)     * 64 + 2 * lane];
            float2 w1 = *(const float2*)&Ws[(2 * kk + 1) * 64 + 2 * lane];
#pragma unroll
            for (int t = 0; t < 8; t++) {
                float x0 = __shfl_sync(0xffffffffu, v[t].x, kk);
                float x1 = __shfl_sync(0xffffffffu, v[t].y, kk);
                a[t].x = fmaf(x0, w0.x, fmaf(x1, w1.x, a[t].x));
                a[t].y = fmaf(x0, w0.y, fmaf(x1, w1.y, a[t].y));
            }
        }

        float2 p[8];
#pragma unroll
        for (int t = 0; t < 8; t++) p[t] = bb3;
#pragma unroll 4
        for (int kk = 0; kk < 32; kk++) {
            float2 w0 = *(const float2*)&Ws[4096 + (2 * kk)     * 64 + 2 * lane];
            float2 w1 = *(const float2*)&Ws[4096 + (2 * kk + 1) * 64 + 2 * lane];
#pragma unroll
            for (int t = 0; t < 8; t++) {
                float x0 = __shfl_sync(0xffffffffu, a[t].x, kk);
                float x1 = __shfl_sync(0xffffffffu, a[t].y, kk);
                p[t].x = fmaf(x0, w0.x, fmaf(x1, w1.x, p[t].x));
                p[t].y = fmaf(x0, w0.y, fmaf(x1, w1.y, p[t].y));
            }
        }
#pragma unroll
        for (int t = 0; t < 8; t++) {
            p[t].x *= fsig(p[t].x);
            p[t].y *= fsig(p[t].y);
        }

        float2 q[8];
#pragma unroll
        for (int t = 0; t < 8; t++) q[t] = bb4;
#pragma unroll 4
        for (int kk = 0; kk < 32; kk++) {
            float2 w0 = *(const float2*)&Ws[8192 + (2 * kk)     * 64 + 2 * lane];
            float2 w1 = *(const float2*)&Ws[8192 + (2 * kk + 1) * 64 + 2 * lane];
#pragma unroll
            for (int t = 0; t < 8; t++) {
                float x0 = __shfl_sync(0xffffffffu, p[t].x, kk);
                float x1 = __shfl_sync(0xffffffffu, p[t].y, kk);
                q[t].x = fmaf(x0, w0.x, fmaf(x1, w1.x, q[t].x));
                q[t].y = fmaf(x0, w0.y, fmaf(x1, w1.y, q[t].y));
            }
        }
#pragma unroll
        for (int t = 0; t < 8; t++) {
            int n = n0 + t;
            if (n < N) {
                float2 xv = *(const float2*)&x[(size_t)n * 64 + 2 * lane];
                *(float2*)&out[(size_t)n * 64 + 2 * lane] =
                    make_float2(xv.x + q[t].x, xv.y + q[t].y);
            }
        }
    }
}

// ---------------------------------------------------------------------------
extern "C" void kernel_launch(void* const* d_in, const int* in_sizes, int n_in,
                              void* d_out, int out_size)
{
    const float* x   = (const float*)d_in[0];
    const float* rbf = (const float*)d_in[2];
    const int*   eidx = (const int*)d_in[3];
    const float* W1 = (const float*)d_in[4];
    const float* b1 = (const float*)d_in[5];
    const float* W2 = (const float*)d_in[6];
    const float* b2 = (const float*)d_in[7];
    const float* W3 = (const float*)d_in[8];
    const float* b3 = (const float*)d_in[9];
    const float* W4 = (const float*)d_in[10];
    const float* b4 = (const float*)d_in[11];
    float* out = (float*)d_out;

    int E = in_sizes[3] / 2;
    int N = in_sizes[0] / EMB;
    int nblk = (N + 511) / 512;

    hist_kernel<<<(E + 255) / 256, 256>>>(eidx, E);
    scan_kernel<<<nblk, 512>>>(N, E);
    permute_kernel<<<(E + 255) / 256, 256>>>(eidx, E);
    edge_gather_kernel<<<592, 256>>>(rbf, W1, b1, N);
    node_kernel<<<592, 256>>>(x, W2, b2, W3, b3, W4, b4, out, N);
}